// round 10
// baseline (speedup 1.0000x reference)
#include <cuda_runtime.h>

#define NB    64
#define PW    68      // 64 + 2*2 halo
#define BUF   4624    // 68*68
#define NPIX  4096
#define NTH   512

// Prep outputs (device-global scratch: no allocation allowed)
__device__ float g_T[104];    // T[tap][z], z in 0..3 (3 = zero-pad sentinel)
__device__ float g_effb;
__device__ float g_wfc[100];  // wfc[o][25] = sum_a fc[o,a] * w[a]

// ---------------------------------------------------------------------------
// Prep: collapse encode_w(150x2x5x5)+r_w(150)+emb(3x2) -> 25-tap x 4-symbol LUT
// and fold fc into the final conv weights: wfc[o] = sum_a fc[o,a] * w_a.
// ---------------------------------------------------------------------------
__global__ void prep_kernel(const float* __restrict__ emb,
                            const float* __restrict__ encode_w,
                            const float* __restrict__ encode_b,
                            const float* __restrict__ r_w,
                            const float* __restrict__ w_in,
                            const float* __restrict__ fc_w) {
    __shared__ float effw[50];
    int t = threadIdx.x;   // 128 threads
    if (t < 50) {
        float s = 0.f;
        for (int c = 0; c < 150; ++c) s = fmaf(r_w[c], encode_w[c * 50 + t], s);
        effw[t] = s;
    }
    __syncthreads();
    if (t < 25) {
        float w0 = effw[t], w1 = effw[25 + t];
        #pragma unroll
        for (int z = 0; z < 3; ++z)
            g_T[t * 4 + z] = w0 * emb[2 * z] + w1 * emb[2 * z + 1];
        g_T[t * 4 + 3] = 0.f;
    } else if (t == 27) {
        float s = 0.f;
        for (int c = 0; c < 150; ++c) s = fmaf(r_w[c], encode_b[c], s);
        g_effb = s;
    } else if (t >= 28 && t < 128) {
        int idx = t - 28;            // 0..99
        int o = idx / 25, k = idx % 25;
        float s = 0.f;
        #pragma unroll
        for (int a = 0; a < 8; ++a)
            s = fmaf(fc_w[o * 8 + a], w_in[a * 25 + k], s);
        g_wfc[idx] = s;
    }
}

// ---------------------------------------------------------------------------
// Fused VIN: 1 CTA per image, 512 threads, everything in SMEM.
// x = tid&63, strip s = tid>>6 owns rows 8s..8s+7 (lane-stride-1 LDS).
// ---------------------------------------------------------------------------
__global__ __launch_bounds__(NTH, 1)
void vin_kernel(const int* __restrict__ maze,
                const float* __restrict__ q_w,
                const float* __restrict__ w_in,
                const float* __restrict__ fc_w,
                float* __restrict__ out) {
    extern __shared__ float sm[];
    float* bufA  = sm;                  // v ping (zero halo)
    float* bufB  = sm + BUF;            // v pong (doubles as maze tile in setup)
    float* r_s   = sm + 2 * BUF;        // r with zero halo
    float* Rq_s  = sm + 3 * BUF;        // [8][4096] iteration-invariant conv(r, q_w)
    float* T_s   = Rq_s + 8 * NPIX;     // 104
    float* qw_s  = T_s + 104;           // 200
    float* w_s   = qw_s + 200;          // 200
    float* wfc_s = w_s + 200;           // 100
    float* fc_s  = wfc_s + 100;         // 32

    const int tid = threadIdx.x;
    const int b   = blockIdx.x;
    const int x   = tid & 63;
    const int ys  = (tid >> 6) << 3;    // first output row of this strip

    int* m_tile = (int*)bufB;

    // --- init: zero halos, sentinel-pad maze tile, stage coefficients
    for (int i = tid; i < BUF; i += NTH) { bufA[i] = 0.f; r_s[i] = 0.f; m_tile[i] = 3; }
    for (int i = tid; i < 200; i += NTH) { qw_s[i] = q_w[i]; w_s[i] = w_in[i]; }
    if (tid < 104) T_s[tid] = g_T[tid];
    if (tid < 100) wfc_s[tid] = g_wfc[tid];
    if (tid < 32)  fc_s[tid] = fc_w[tid];
    __syncthreads();

    const int* mz = maze + b * NPIX;
    for (int i = tid; i < NPIX; i += NTH)
        m_tile[((i >> 6) + 2) * PW + (i & 63) + 2] = mz[i];
    __syncthreads();

    // --- phase 1: r = eff_b + sum_tap T[tap][maze(window)]
    {
        int mwin[12][5];
        #pragma unroll
        for (int dy = 0; dy < 12; ++dy)
            #pragma unroll
            for (int dx = 0; dx < 5; ++dx)
                mwin[dy][dx] = m_tile[(ys + dy) * PW + x + dx];
        float eb = g_effb;
        float racc[8];
        #pragma unroll
        for (int j = 0; j < 8; ++j) racc[j] = eb;
        #pragma unroll
        for (int ky = 0; ky < 5; ++ky)
            #pragma unroll
            for (int kx = 0; kx < 5; ++kx) {
                const float* Tr = T_s + (ky * 5 + kx) * 4;
                #pragma unroll
                for (int j = 0; j < 8; ++j)
                    racc[j] += Tr[mwin[j + ky][kx]];
            }
        #pragma unroll
        for (int j = 0; j < 8; ++j)
            r_s[(ys + j + 2) * PW + x + 2] = racc[j];
    }
    __syncthreads();

    // --- phase 2: Rq = conv(r, q_w) (kept in SMEM), v1 = max_a Rq; re-zero bufB
    {
        float rwin[12][5];
        #pragma unroll
        for (int dy = 0; dy < 12; ++dy)
            #pragma unroll
            for (int dx = 0; dx < 5; ++dx)
                rwin[dy][dx] = r_s[(ys + dy) * PW + x + dx];
        float vmax[8];
        #pragma unroll
        for (int a = 0; a < 8; ++a) {
            float acc[8] = {0.f,0.f,0.f,0.f,0.f,0.f,0.f,0.f};
            #pragma unroll
            for (int ky = 0; ky < 5; ++ky)
                #pragma unroll
                for (int kx = 0; kx < 5; ++kx) {
                    float c = qw_s[a * 25 + ky * 5 + kx];
                    #pragma unroll
                    for (int j = 0; j < 8; ++j)
                        acc[j] = fmaf(c, rwin[j + ky][kx], acc[j]);
                }
            #pragma unroll
            for (int j = 0; j < 8; ++j) {
                Rq_s[a * NPIX + (ys + j) * 64 + x] = acc[j];
                vmax[j] = (a == 0) ? acc[j] : fmaxf(vmax[j], acc[j]);
            }
        }
        #pragma unroll
        for (int j = 0; j < 8; ++j)
            bufA[(ys + j + 2) * PW + x + 2] = vmax[j];
        for (int i = tid; i < BUF; i += NTH) bufB[i] = 0.f;  // clear maze sentinels
    }
    __syncthreads();

    // --- 9 value-iteration steps; Rq folded into accumulator init (no FADD)
    float* vin  = bufA;
    float* vout = bufB;
    for (int t = 0; t < 9; ++t) {
        float vw[12][5];
        #pragma unroll
        for (int dy = 0; dy < 12; ++dy)
            #pragma unroll
            for (int dx = 0; dx < 5; ++dx)
                vw[dy][dx] = vin[(ys + dy) * PW + x + dx];
        float vmax[8];
        #pragma unroll
        for (int a = 0; a < 8; ++a) {
            const float* rqa = Rq_s + a * NPIX + ys * 64 + x;
            float acc[8];
            #pragma unroll
            for (int j = 0; j < 8; ++j) acc[j] = rqa[j * 64];
            #pragma unroll
            for (int ky = 0; ky < 5; ++ky)
                #pragma unroll
                for (int kx = 0; kx < 5; ++kx) {
                    float c = w_s[a * 25 + ky * 5 + kx];
                    #pragma unroll
                    for (int j = 0; j < 8; ++j)
                        acc[j] = fmaf(c, vw[j + ky][kx], acc[j]);
                }
            #pragma unroll
            for (int j = 0; j < 8; ++j)
                vmax[j] = (a == 0) ? acc[j] : fmaxf(vmax[j], acc[j]);
        }
        #pragma unroll
        for (int j = 0; j < 8; ++j)
            vout[(ys + j + 2) * PW + x + 2] = vmax[j];
        __syncthreads();
        float* tmp = vin; vin = vout; vout = tmp;
    }

    // --- final step with fc folded into the conv:
    //     out[o] = sum_a fc[o,a]*Rq_a + conv(v10, wfc_o)   (4 convs, not 8)
    {
        float vw[12][5];
        #pragma unroll
        for (int dy = 0; dy < 12; ++dy)
            #pragma unroll
            for (int dx = 0; dx < 5; ++dx)
                vw[dy][dx] = vin[(ys + dy) * PW + x + dx];
        float4* op = (float4*)(out + (size_t)b * NPIX * 4);
        #pragma unroll
        for (int j = 0; j < 8; ++j) {
            float o0 = 0.f, o1 = 0.f, o2 = 0.f, o3 = 0.f;
            #pragma unroll
            for (int a = 0; a < 8; ++a) {
                float rq = Rq_s[a * NPIX + (ys + j) * 64 + x];
                o0 = fmaf(fc_s[a],      rq, o0);
                o1 = fmaf(fc_s[8 + a],  rq, o1);
                o2 = fmaf(fc_s[16 + a], rq, o2);
                o3 = fmaf(fc_s[24 + a], rq, o3);
            }
            #pragma unroll
            for (int ky = 0; ky < 5; ++ky)
                #pragma unroll
                for (int kx = 0; kx < 5; ++kx) {
                    float v = vw[j + ky][kx];
                    o0 = fmaf(wfc_s[ky * 5 + kx],      v, o0);
                    o1 = fmaf(wfc_s[25 + ky * 5 + kx], v, o1);
                    o2 = fmaf(wfc_s[50 + ky * 5 + kx], v, o2);
                    o3 = fmaf(wfc_s[75 + ky * 5 + kx], v, o3);
                }
            op[(ys + j) * 64 + x] = make_float4(o0, o1, o2, o3);
        }
    }
}

// ---------------------------------------------------------------------------
extern "C" void kernel_launch(void* const* d_in, const int* in_sizes, int n_in,
                              void* d_out, int out_size) {
    const int*   maze     = (const int*)d_in[0];
    const float* emb      = (const float*)d_in[1];
    const float* encode_w = (const float*)d_in[2];
    const float* encode_b = (const float*)d_in[3];
    const float* r_w      = (const float*)d_in[4];
    const float* q_w      = (const float*)d_in[5];
    const float* w_in     = (const float*)d_in[6];
    const float* fc_w     = (const float*)d_in[7];
    float* out = (float*)d_out;

    prep_kernel<<<1, 128>>>(emb, encode_w, encode_b, r_w, w_in, fc_w);

    const int smem_bytes = (3 * BUF + 8 * NPIX + 104 + 200 + 200 + 100 + 32)
                           * (int)sizeof(float);
    cudaFuncSetAttribute(vin_kernel,
                         cudaFuncAttributeMaxDynamicSharedMemorySize, smem_bytes);
    vin_kernel<<<NB, NTH, smem_bytes>>>(maze, q_w, w_in, fc_w, out);
}

// round 11
// speedup vs baseline: 1.6488x; 1.6488x over previous
#include <cuda_runtime.h>
#include <cstdint>

#define NB    64
#define PW    68          // 64 + 2+2 x-halo
#define ROWS  32          // rows owned per CTA
#define VROWS 36          // 32 + 2+2 y-halo
#define VBUF  (VROWS*PW)  // 2448
#define MROWS 40
#define NPIX  4096
#define NTH   512

__device__ float g_T[104];
__device__ float g_effb;
__device__ float g_wfc[100];  // wfc[o][25] = sum_a fc[o,a] * w[a]

// ---------------------------------------------------------------------------
__global__ void prep_kernel(const float* __restrict__ emb,
                            const float* __restrict__ encode_w,
                            const float* __restrict__ encode_b,
                            const float* __restrict__ r_w,
                            const float* __restrict__ w_in,
                            const float* __restrict__ fc_w) {
    __shared__ float effw[50];
    int t = threadIdx.x;   // 128 threads
    if (t < 50) {
        float s = 0.f;
        for (int c = 0; c < 150; ++c) s = fmaf(r_w[c], encode_w[c * 50 + t], s);
        effw[t] = s;
    }
    __syncthreads();
    if (t < 25) {
        float w0 = effw[t], w1 = effw[25 + t];
        #pragma unroll
        for (int z = 0; z < 3; ++z)
            g_T[t * 4 + z] = w0 * emb[2 * z] + w1 * emb[2 * z + 1];
        g_T[t * 4 + 3] = 0.f;
    } else if (t == 27) {
        float s = 0.f;
        for (int c = 0; c < 150; ++c) s = fmaf(r_w[c], encode_b[c], s);
        g_effb = s;
    } else if (t >= 28 && t < 128) {
        int idx = t - 28;            // 0..99
        int o = idx / 25, k = idx % 25;
        float s = 0.f;
        #pragma unroll
        for (int a = 0; a < 8; ++a)
            s = fmaf(fc_w[o * 8 + a], w_in[a * 25 + k], s);
        g_wfc[idx] = s;
    }
}

// -------- cluster / mbarrier helpers ---------------------------------------
__device__ __forceinline__ void st_remote_f32(float* p, uint32_t peer, float v) {
    uint32_t a = (uint32_t)__cvta_generic_to_shared(p);
    uint32_t ra;
    asm("mapa.shared::cluster.u32 %0, %1, %2;" : "=r"(ra) : "r"(a), "r"(peer));
    asm volatile("st.shared::cluster.f32 [%0], %1;" :: "r"(ra), "f"(v) : "memory");
}
__device__ __forceinline__ void mbar_init(uint32_t bar, uint32_t count) {
    asm volatile("mbarrier.init.shared.b64 [%0], %1;" :: "r"(bar), "r"(count) : "memory");
}
// producer: arrive (release, cluster scope) on the PEER CTA's barrier
__device__ __forceinline__ void mbar_arrive_peer(uint32_t bar, uint32_t peer) {
    uint32_t ra;
    asm("mapa.shared::cluster.u32 %0, %1, %2;" : "=r"(ra) : "r"(bar), "r"(peer));
    asm volatile("mbarrier.arrive.release.cluster.shared::cluster.b64 _, [%0];"
                 :: "r"(ra) : "memory");
}
// consumer: spin on local barrier with cluster-scope acquire
__device__ __forceinline__ void mbar_wait_cluster(uint32_t bar, uint32_t parity) {
    asm volatile(
        "{\n\t.reg .pred P;\n\t"
        "W%=:\n\t"
        "mbarrier.try_wait.parity.acquire.cluster.shared::cta.b64 P, [%0], %1;\n\t"
        "@P bra D%=;\n\t"
        "bra W%=;\n\t"
        "D%=:\n\t}"
        :: "r"(bar), "r"(parity) : "memory");
}
__device__ __forceinline__ void cluster_sync_all() {
    asm volatile("barrier.cluster.arrive.aligned;" ::: "memory");
    asm volatile("barrier.cluster.wait.aligned;" ::: "memory");
}

// ---------------------------------------------------------------------------
// VIN: 2-CTA cluster per image, point-to-point mbarrier halo handshake.
// rank0 owns rows 0..31, rank1 rows 32..63. Buffer row = local row + 2.
// 512 threads: x = tid&63, strip s = tid>>6 owns local rows 4s..4s+3.
// Only the seam strip (rank0:s7 / rank1:s0) waits; it also produces the
// peer's 2 halo rows (st.shared::cluster + arrive.release on peer barrier).
// ---------------------------------------------------------------------------
__global__ __launch_bounds__(NTH, 1) __cluster_dims__(2, 1, 1)
void vin_kernel(const int* __restrict__ maze,
                const float* __restrict__ q_w,
                const float* __restrict__ w_in,
                const float* __restrict__ fc_w,
                float* __restrict__ out) {
    extern __shared__ float sm[];
    float* bufA  = sm;                   // v ping
    float* bufB  = sm + VBUF;            // v pong
    float* r_s   = sm + 2 * VBUF;        // r (local rows -2..33 at buf rows 0..35)
    float* Rq_s  = sm + 3 * VBUF;        // [8][32][64]
    float* T_s   = Rq_s + 8 * ROWS * 64; // 104
    float* qw_s  = T_s + 104;            // 200
    float* w_s   = qw_s + 200;           // 200
    float* wfc_s = w_s + 200;            // 100
    float* fc_s  = wfc_s + 100;          // 32
    uint32_t mbar = (uint32_t)__cvta_generic_to_shared(fc_s + 32); // 8B, even offset

    const int tid  = threadIdx.x;
    const int b    = blockIdx.x >> 1;
    const uint32_t rank = blockIdx.x & 1;
    const uint32_t peer = rank ^ 1u;
    const int base = (int)rank * ROWS;
    const int x    = tid & 63;
    const int s    = tid >> 6;           // 0..7
    const int l0   = s << 2;             // first own local row
    const bool seam = rank ? (s == 0) : (s == 7);

    int* m_tile = (int*)Rq_s;            // 40x68 ints alias, dead before Rq use

    // --- init
    for (int i = tid; i < VBUF; i += NTH) { bufA[i] = 0.f; bufB[i] = 0.f; r_s[i] = 0.f; }
    for (int i = tid; i < MROWS * PW; i += NTH) m_tile[i] = 3;
    for (int i = tid; i < 200; i += NTH) { qw_s[i] = q_w[i]; w_s[i] = w_in[i]; }
    if (tid < 104) T_s[tid] = g_T[tid];
    if (tid < 100) wfc_s[tid] = g_wfc[tid];
    if (tid < 32)  fc_s[tid] = fc_w[tid];
    if (tid == 0)  mbar_init(mbar, 64);
    __syncthreads();
    cluster_sync_all();   // both barriers initialized before any remote arrive

    const int* mz = maze + b * NPIX;
    for (int i = tid; i < MROWS * 64; i += NTH) {
        int lr = i >> 6;                 // global row = base-4+lr
        int gr = base - 4 + lr;
        int gc = i & 63;
        if (gr >= 0 && gr < 64)
            m_tile[lr * PW + gc + 2] = mz[gr * 64 + gc];
    }
    __syncthreads();

    // --- phase 1: r on local rows -2..33 (in-image only), buf row = local+2
    {
        const float effb = g_effb;
        for (int p = tid; p < VROWS * 64; p += NTH) {
            int lr = p >> 6;             // local row = lr-2
            int gr = base - 2 + lr;
            int gc = p & 63;
            if (gr < 0 || gr >= 64) continue;
            float acc = effb;
            #pragma unroll
            for (int ky = 0; ky < 5; ++ky)
                #pragma unroll
                for (int kx = 0; kx < 5; ++kx)
                    acc += T_s[(ky * 5 + kx) * 4 + m_tile[(lr + ky) * PW + gc + kx]];
            r_s[lr * PW + gc + 2] = acc;
        }
    }
    __syncthreads();   // m_tile dead

    // --- phase 2: Rq = conv(r, q_w), v1 = max_a Rq; push halos, arrive round 0
    {
        float rwin[8][5];
        #pragma unroll
        for (int dy = 0; dy < 8; ++dy)
            #pragma unroll
            for (int dx = 0; dx < 5; ++dx)
                rwin[dy][dx] = r_s[(l0 + dy) * PW + x + dx];
        float vmax[4];
        #pragma unroll
        for (int a = 0; a < 8; ++a) {
            float acc[4] = {0.f, 0.f, 0.f, 0.f};
            #pragma unroll
            for (int ky = 0; ky < 5; ++ky)
                #pragma unroll
                for (int kx = 0; kx < 5; ++kx) {
                    float c = qw_s[a * 25 + ky * 5 + kx];
                    #pragma unroll
                    for (int j = 0; j < 4; ++j)
                        acc[j] = fmaf(c, rwin[j + ky][kx], acc[j]);
                }
            #pragma unroll
            for (int j = 0; j < 4; ++j) {
                Rq_s[a * (ROWS * 64) + (l0 + j) * 64 + x] = acc[j];
                vmax[j] = (a == 0) ? acc[j] : fmaxf(vmax[j], acc[j]);
            }
        }
        #pragma unroll
        for (int j = 0; j < 4; ++j)
            bufA[(l0 + j + 2) * PW + x + 2] = vmax[j];
        if (seam) {
            if (rank == 0) {   // own rows 30,31 -> peer buf rows 0,1
                st_remote_f32(&bufA[0 * PW + x + 2], peer, vmax[2]);
                st_remote_f32(&bufA[1 * PW + x + 2], peer, vmax[3]);
            } else {           // own rows 32,33 -> peer buf rows 34,35
                st_remote_f32(&bufA[34 * PW + x + 2], peer, vmax[0]);
                st_remote_f32(&bufA[35 * PW + x + 2], peer, vmax[1]);
            }
            mbar_arrive_peer(mbar, peer);   // round 0
        }
    }
    __syncthreads();

    // --- 9 value-iteration steps; only seam strip touches the mbarrier
    float* vin  = bufA;
    float* vout = bufB;
    #pragma unroll 1
    for (int k = 0; k < 9; ++k) {
        if (seam) mbar_wait_cluster(mbar, (uint32_t)(k & 1));   // round k done
        float vw[8][5];
        #pragma unroll
        for (int dy = 0; dy < 8; ++dy)
            #pragma unroll
            for (int dx = 0; dx < 5; ++dx)
                vw[dy][dx] = vin[(l0 + dy) * PW + x + dx];
        float vmax[4];
        #pragma unroll
        for (int a = 0; a < 8; ++a) {
            const float* rqa = Rq_s + a * (ROWS * 64) + l0 * 64 + x;
            float acc[4];
            #pragma unroll
            for (int j = 0; j < 4; ++j) acc[j] = rqa[j * 64];
            #pragma unroll
            for (int ky = 0; ky < 5; ++ky)
                #pragma unroll
                for (int kx = 0; kx < 5; ++kx) {
                    float c = w_s[a * 25 + ky * 5 + kx];
                    #pragma unroll
                    for (int j = 0; j < 4; ++j)
                        acc[j] = fmaf(c, vw[j + ky][kx], acc[j]);
                }
            #pragma unroll
            for (int j = 0; j < 4; ++j)
                vmax[j] = (a == 0) ? acc[j] : fmaxf(vmax[j], acc[j]);
        }
        #pragma unroll
        for (int j = 0; j < 4; ++j)
            vout[(l0 + j + 2) * PW + x + 2] = vmax[j];
        if (seam) {
            if (rank == 0) {
                st_remote_f32(&vout[0 * PW + x + 2], peer, vmax[2]);
                st_remote_f32(&vout[1 * PW + x + 2], peer, vmax[3]);
            } else {
                st_remote_f32(&vout[34 * PW + x + 2], peer, vmax[0]);
                st_remote_f32(&vout[35 * PW + x + 2], peer, vmax[1]);
            }
            mbar_arrive_peer(mbar, peer);   // round k+1
        }
        __syncthreads();
        float* tmp = vin; vin = vout; vout = tmp;
    }

    // --- final: out[o] = sum_a fc[o,a]*Rq_a + conv(v10, wfc_o)  (4 convs)
    {
        if (seam) mbar_wait_cluster(mbar, 1u);   // round 9
        float vw[8][5];
        #pragma unroll
        for (int dy = 0; dy < 8; ++dy)
            #pragma unroll
            for (int dx = 0; dx < 5; ++dx)
                vw[dy][dx] = vin[(l0 + dy) * PW + x + dx];
        float4* op = (float4*)(out + (size_t)b * NPIX * 4);
        #pragma unroll
        for (int j = 0; j < 4; ++j) {
            float o0 = 0.f, o1 = 0.f, o2 = 0.f, o3 = 0.f;
            #pragma unroll
            for (int a = 0; a < 8; ++a) {
                float rq = Rq_s[a * (ROWS * 64) + (l0 + j) * 64 + x];
                o0 = fmaf(fc_s[a],      rq, o0);
                o1 = fmaf(fc_s[8 + a],  rq, o1);
                o2 = fmaf(fc_s[16 + a], rq, o2);
                o3 = fmaf(fc_s[24 + a], rq, o3);
            }
            #pragma unroll
            for (int ky = 0; ky < 5; ++ky)
                #pragma unroll
                for (int kx = 0; kx < 5; ++kx) {
                    float v = vw[j + ky][kx];
                    o0 = fmaf(wfc_s[ky * 5 + kx],      v, o0);
                    o1 = fmaf(wfc_s[25 + ky * 5 + kx], v, o1);
                    o2 = fmaf(wfc_s[50 + ky * 5 + kx], v, o2);
                    o3 = fmaf(wfc_s[75 + ky * 5 + kx], v, o3);
                }
            op[(base + l0 + j) * 64 + x] = make_float4(o0, o1, o2, o3);
        }
    }
    __syncthreads();
    cluster_sync_all();   // no CTA exits while peer may still map its SMEM
}

// ---------------------------------------------------------------------------
extern "C" void kernel_launch(void* const* d_in, const int* in_sizes, int n_in,
                              void* d_out, int out_size) {
    const int*   maze     = (const int*)d_in[0];
    const float* emb      = (const float*)d_in[1];
    const float* encode_w = (const float*)d_in[2];
    const float* encode_b = (const float*)d_in[3];
    const float* r_w      = (const float*)d_in[4];
    const float* q_w      = (const float*)d_in[5];
    const float* w_in     = (const float*)d_in[6];
    const float* fc_w     = (const float*)d_in[7];
    float* out = (float*)d_out;

    prep_kernel<<<1, 128>>>(emb, encode_w, encode_b, r_w, w_in, fc_w);

    const int smem_bytes = (3 * VBUF + 8 * ROWS * 64 + 104 + 200 + 200 + 100 + 32 + 4)
                           * (int)sizeof(float);
    cudaFuncSetAttribute(vin_kernel,
                         cudaFuncAttributeMaxDynamicSharedMemorySize, smem_bytes);
    vin_kernel<<<NB * 2, NTH, smem_bytes>>>(maze, q_w, w_in, fc_w, out);
}

// round 12
// speedup vs baseline: 2.0015x; 1.2139x over previous
#include <cuda_runtime.h>
#include <cstdint>

#define NB    64
#define PW    68          // 64 + 2+2 x-halo
#define ROWS  32          // rows owned per CTA
#define VROWS 36          // 32 + 2+2 y-halo
#define VBUF  (VROWS*PW)  // 2448
#define MROWS 40
#define NPIX  4096
#define NTH   512

// -------- cluster / mbarrier helpers ---------------------------------------
__device__ __forceinline__ void st_remote_f32(float* p, uint32_t peer, float v) {
    uint32_t a = (uint32_t)__cvta_generic_to_shared(p);
    uint32_t ra;
    asm("mapa.shared::cluster.u32 %0, %1, %2;" : "=r"(ra) : "r"(a), "r"(peer));
    asm volatile("st.shared::cluster.f32 [%0], %1;" :: "r"(ra), "f"(v) : "memory");
}
__device__ __forceinline__ void mbar_init(uint32_t bar, uint32_t count) {
    asm volatile("mbarrier.init.shared.b64 [%0], %1;" :: "r"(bar), "r"(count) : "memory");
}
__device__ __forceinline__ void mbar_arrive_peer(uint32_t bar, uint32_t peer) {
    uint32_t ra;
    asm("mapa.shared::cluster.u32 %0, %1, %2;" : "=r"(ra) : "r"(bar), "r"(peer));
    asm volatile("mbarrier.arrive.release.cluster.shared::cluster.b64 _, [%0];"
                 :: "r"(ra) : "memory");
}
__device__ __forceinline__ void mbar_wait_cluster(uint32_t bar, uint32_t parity) {
    asm volatile(
        "{\n\t.reg .pred P;\n\t"
        "W%=:\n\t"
        "mbarrier.try_wait.parity.acquire.cluster.shared::cta.b64 P, [%0], %1;\n\t"
        "@P bra D%=;\n\t"
        "bra W%=;\n\t"
        "D%=:\n\t}"
        :: "r"(bar), "r"(parity) : "memory");
}
__device__ __forceinline__ void cluster_sync_all() {
    asm volatile("barrier.cluster.arrive.aligned;" ::: "memory");
    asm volatile("barrier.cluster.wait.aligned;" ::: "memory");
}

// ---------------------------------------------------------------------------
// VIN: 2-CTA cluster per image, p2p mbarrier halo handshake (R10 structure),
// prep folded in, vectorized weight/Rq SMEM accesses.
// rank0 owns rows 0..31, rank1 rows 32..63. Buffer row = local row + 2.
// 512 threads: x = tid&63, strip s = tid>>6 owns local rows 4s..4s+3.
// Weight layout: [a][ky][8] (5 taps + 3 pad) -> 2 aligned float4 per row.
// Rq layout: thread-private float4 Rq4[a*512 + tid] (writer == reader).
// ---------------------------------------------------------------------------
__global__ __launch_bounds__(NTH, 1) __cluster_dims__(2, 1, 1)
void vin_kernel(const int* __restrict__ maze,
                const float* __restrict__ emb,
                const float* __restrict__ encode_w,
                const float* __restrict__ encode_b,
                const float* __restrict__ r_w,
                const float* __restrict__ q_w,
                const float* __restrict__ w_in,
                const float* __restrict__ fc_w,
                float* __restrict__ out) {
    extern __shared__ float sm[];
    float* bufA  = sm;                    // 2448  v ping
    float* bufB  = sm + VBUF;             // 2448  v pong
    float* r_s   = sm + 2 * VBUF;         // 2448  r
    float* Rq_s  = sm + 3 * VBUF;         // 16384 (16B-aligned: 7344*4/16 int)
    float* qw8   = Rq_s + 8 * 2048;       // 320   padded q_w
    float* w8    = qw8 + 320;             // 320   padded w
    float* wfc8  = w8 + 320;              // 160   padded fc-folded final weights
    float* fc_s  = wfc8 + 160;            // 32
    float* T_s   = fc_s + 32;             // 104   LUT
    float* sb    = T_s + 104;             // 2     [0]=effb
    uint32_t mbar = (uint32_t)__cvta_generic_to_shared(sb + 2);  // 8B aligned

    float4* Rq4 = (float4*)Rq_s;

    const int tid  = threadIdx.x;
    const int b    = blockIdx.x >> 1;
    const uint32_t rank = blockIdx.x & 1;
    const uint32_t peer = rank ^ 1u;
    const int base = (int)rank * ROWS;
    const int x    = tid & 63;
    const int s    = tid >> 6;            // 0..7
    const int l0   = s << 2;              // first own local row
    const bool seam = rank ? (s == 0) : (s == 7);

    int*   m_tile = (int*)Rq_s;           // 40x68 ints alias (floats 0..2719)
    float* effw   = Rq_s + 4096;          // 50-float temp, disjoint from m_tile

    // --- Block A: zero-init everything written sparsely later
    for (int i = tid; i < VBUF; i += NTH) { bufA[i] = 0.f; bufB[i] = 0.f; r_s[i] = 0.f; }
    for (int i = tid; i < MROWS * PW; i += NTH) m_tile[i] = 3;
    for (int i = tid; i < 320; i += NTH) { qw8[i] = 0.f; w8[i] = 0.f; }
    for (int i = tid; i < 160; i += NTH) wfc8[i] = 0.f;
    if (tid < 32) fc_s[tid] = fc_w[tid];
    if (tid == 0) mbar_init(mbar, 64);
    __syncthreads();
    cluster_sync_all();   // both mbarriers live before any remote arrive

    // --- Block B: maze load + weight scatter + effw chain (prep folded in)
    const int* mz = maze + b * NPIX;
    for (int i = tid; i < MROWS * 64; i += NTH) {
        int lr = i >> 6;                  // global row = base-4+lr
        int gr = base - 4 + lr;
        int gc = i & 63;
        if (gr >= 0 && gr < 64)
            m_tile[lr * PW + gc + 2] = mz[gr * 64 + gc];
    }
    for (int i = tid; i < 200; i += NTH) {
        int a = i / 25, k = i % 25;
        int idx = a * 40 + (k / 5) * 8 + (k % 5);
        qw8[idx] = q_w[i];
        w8[idx]  = w_in[i];
    }
    if (tid < 50) {
        float ssum = 0.f;
        for (int c = 0; c < 150; ++c) ssum = fmaf(r_w[c], encode_w[c * 50 + tid], ssum);
        effw[tid] = ssum;
    }
    __syncthreads();

    // --- Block C: LUT T, effb, fc-folded final weights
    if (tid < 25) {
        float w0 = effw[tid], w1 = effw[25 + tid];
        #pragma unroll
        for (int z = 0; z < 3; ++z)
            T_s[tid * 4 + z] = w0 * emb[2 * z] + w1 * emb[2 * z + 1];
        T_s[tid * 4 + 3] = 0.f;
    } else if (tid == 27) {
        float ssum = 0.f;
        for (int c = 0; c < 150; ++c) ssum = fmaf(r_w[c], encode_b[c], ssum);
        sb[0] = ssum;
    } else if (tid >= 32 && tid < 132) {
        int idx = tid - 32;               // 0..99
        int o = idx / 25, k = idx % 25;
        float ssum = 0.f;
        #pragma unroll
        for (int a = 0; a < 8; ++a)
            ssum = fmaf(fc_w[o * 8 + a], w_in[a * 25 + k], ssum);
        wfc8[o * 40 + (k / 5) * 8 + (k % 5)] = ssum;
    }
    __syncthreads();

    // --- phase 1: r on local rows -2..33 (buf row = local+2), in-image only
    {
        const float effb = sb[0];
        for (int p = tid; p < VROWS * 64; p += NTH) {
            int lr = p >> 6;              // local row = lr-2
            int gr = base - 2 + lr;
            int gc = p & 63;
            if (gr < 0 || gr >= 64) continue;
            float acc = effb;
            #pragma unroll
            for (int ky = 0; ky < 5; ++ky)
                #pragma unroll
                for (int kx = 0; kx < 5; ++kx)
                    acc += T_s[(ky * 5 + kx) * 4 + m_tile[(lr + ky) * PW + gc + kx]];
            r_s[lr * PW + gc + 2] = acc;
        }
    }
    __syncthreads();   // m_tile/effw dead; Rq region writable

    // --- phase 2: Rq = conv(r, q_w), v1 = max_a Rq; push halos, arrive round 0
    {
        float rwin[8][5];
        #pragma unroll
        for (int dy = 0; dy < 8; ++dy)
            #pragma unroll
            for (int dx = 0; dx < 5; ++dx)
                rwin[dy][dx] = r_s[(l0 + dy) * PW + x + dx];
        float vmax[4];
        #pragma unroll
        for (int a = 0; a < 8; ++a) {
            const float4* wv = (const float4*)(qw8 + a * 40);
            float acc[4] = {0.f, 0.f, 0.f, 0.f};
            #pragma unroll
            for (int ky = 0; ky < 5; ++ky) {
                float4 wA = wv[2 * ky], wB = wv[2 * ky + 1];
                #pragma unroll
                for (int j = 0; j < 4; ++j) {
                    acc[j] = fmaf(wA.x, rwin[j + ky][0], acc[j]);
                    acc[j] = fmaf(wA.y, rwin[j + ky][1], acc[j]);
                    acc[j] = fmaf(wA.z, rwin[j + ky][2], acc[j]);
                    acc[j] = fmaf(wA.w, rwin[j + ky][3], acc[j]);
                    acc[j] = fmaf(wB.x, rwin[j + ky][4], acc[j]);
                }
            }
            Rq4[a * 512 + tid] = make_float4(acc[0], acc[1], acc[2], acc[3]);
            #pragma unroll
            for (int j = 0; j < 4; ++j)
                vmax[j] = (a == 0) ? acc[j] : fmaxf(vmax[j], acc[j]);
        }
        #pragma unroll
        for (int j = 0; j < 4; ++j)
            bufA[(l0 + j + 2) * PW + x + 2] = vmax[j];
        if (seam) {
            if (rank == 0) {   // own rows 30,31 -> peer buf rows 0,1
                st_remote_f32(&bufA[0 * PW + x + 2], peer, vmax[2]);
                st_remote_f32(&bufA[1 * PW + x + 2], peer, vmax[3]);
            } else {           // own rows 32,33 -> peer buf rows 34,35
                st_remote_f32(&bufA[34 * PW + x + 2], peer, vmax[0]);
                st_remote_f32(&bufA[35 * PW + x + 2], peer, vmax[1]);
            }
            mbar_arrive_peer(mbar, peer);   // round 0
        }
    }
    __syncthreads();

    // --- 9 value-iteration steps; only the seam strip touches the mbarrier
    float* vin  = bufA;
    float* vout = bufB;
    #pragma unroll 1
    for (int k = 0; k < 9; ++k) {
        if (seam) mbar_wait_cluster(mbar, (uint32_t)(k & 1));   // round k done
        float vw[8][5];
        #pragma unroll
        for (int dy = 0; dy < 8; ++dy)
            #pragma unroll
            for (int dx = 0; dx < 5; ++dx)
                vw[dy][dx] = vin[(l0 + dy) * PW + x + dx];
        float vmax[4];
        #pragma unroll
        for (int a = 0; a < 8; ++a) {
            const float4* wv = (const float4*)(w8 + a * 40);
            float4 rq = Rq4[a * 512 + tid];
            float acc[4] = {rq.x, rq.y, rq.z, rq.w};
            #pragma unroll
            for (int ky = 0; ky < 5; ++ky) {
                float4 wA = wv[2 * ky], wB = wv[2 * ky + 1];
                #pragma unroll
                for (int j = 0; j < 4; ++j) {
                    acc[j] = fmaf(wA.x, vw[j + ky][0], acc[j]);
                    acc[j] = fmaf(wA.y, vw[j + ky][1], acc[j]);
                    acc[j] = fmaf(wA.z, vw[j + ky][2], acc[j]);
                    acc[j] = fmaf(wA.w, vw[j + ky][3], acc[j]);
                    acc[j] = fmaf(wB.x, vw[j + ky][4], acc[j]);
                }
            }
            #pragma unroll
            for (int j = 0; j < 4; ++j)
                vmax[j] = (a == 0) ? acc[j] : fmaxf(vmax[j], acc[j]);
        }
        #pragma unroll
        for (int j = 0; j < 4; ++j)
            vout[(l0 + j + 2) * PW + x + 2] = vmax[j];
        if (seam) {
            if (rank == 0) {
                st_remote_f32(&vout[0 * PW + x + 2], peer, vmax[2]);
                st_remote_f32(&vout[1 * PW + x + 2], peer, vmax[3]);
            } else {
                st_remote_f32(&vout[34 * PW + x + 2], peer, vmax[0]);
                st_remote_f32(&vout[35 * PW + x + 2], peer, vmax[1]);
            }
            mbar_arrive_peer(mbar, peer);   // round k+1
        }
        __syncthreads();
        float* tmp = vin; vin = vout; vout = tmp;
    }

    // --- final: out[o] = sum_a fc[o,a]*Rq_a + conv(v10, wfc_o)  (4 convs)
    {
        if (seam) mbar_wait_cluster(mbar, 1u);   // round 9
        float vw[8][5];
        #pragma unroll
        for (int dy = 0; dy < 8; ++dy)
            #pragma unroll
            for (int dx = 0; dx < 5; ++dx)
                vw[dy][dx] = vin[(l0 + dy) * PW + x + dx];
        float o[4][4];
        #pragma unroll
        for (int j = 0; j < 4; ++j)
            #pragma unroll
            for (int c = 0; c < 4; ++c) o[j][c] = 0.f;
        // Rq part: o[j][c] += fc[c,a] * Rq_a[j]
        #pragma unroll
        for (int a = 0; a < 8; ++a) {
            float4 rq = Rq4[a * 512 + tid];
            float f0 = fc_s[a], f1 = fc_s[8 + a], f2 = fc_s[16 + a], f3 = fc_s[24 + a];
            o[0][0] = fmaf(f0, rq.x, o[0][0]); o[0][1] = fmaf(f1, rq.x, o[0][1]);
            o[0][2] = fmaf(f2, rq.x, o[0][2]); o[0][3] = fmaf(f3, rq.x, o[0][3]);
            o[1][0] = fmaf(f0, rq.y, o[1][0]); o[1][1] = fmaf(f1, rq.y, o[1][1]);
            o[1][2] = fmaf(f2, rq.y, o[1][2]); o[1][3] = fmaf(f3, rq.y, o[1][3]);
            o[2][0] = fmaf(f0, rq.z, o[2][0]); o[2][1] = fmaf(f1, rq.z, o[2][1]);
            o[2][2] = fmaf(f2, rq.z, o[2][2]); o[2][3] = fmaf(f3, rq.z, o[2][3]);
            o[3][0] = fmaf(f0, rq.w, o[3][0]); o[3][1] = fmaf(f1, rq.w, o[3][1]);
            o[3][2] = fmaf(f2, rq.w, o[3][2]); o[3][3] = fmaf(f3, rq.w, o[3][3]);
        }
        // conv part with fc-folded weights (4 output channels)
        #pragma unroll
        for (int c = 0; c < 4; ++c) {
            const float4* wv = (const float4*)(wfc8 + c * 40);
            #pragma unroll
            for (int ky = 0; ky < 5; ++ky) {
                float4 wA = wv[2 * ky], wB = wv[2 * ky + 1];
                #pragma unroll
                for (int j = 0; j < 4; ++j) {
                    o[j][c] = fmaf(wA.x, vw[j + ky][0], o[j][c]);
                    o[j][c] = fmaf(wA.y, vw[j + ky][1], o[j][c]);
                    o[j][c] = fmaf(wA.z, vw[j + ky][2], o[j][c]);
                    o[j][c] = fmaf(wA.w, vw[j + ky][3], o[j][c]);
                    o[j][c] = fmaf(wB.x, vw[j + ky][4], o[j][c]);
                }
            }
        }
        float4* op = (float4*)(out + (size_t)b * NPIX * 4);
        #pragma unroll
        for (int j = 0; j < 4; ++j)
            op[(base + l0 + j) * 64 + x] = make_float4(o[j][0], o[j][1], o[j][2], o[j][3]);
    }
    __syncthreads();
    cluster_sync_all();   // no CTA exits while peer may still map its SMEM
}

// ---------------------------------------------------------------------------
extern "C" void kernel_launch(void* const* d_in, const int* in_sizes, int n_in,
                              void* d_out, int out_size) {
    const int*   maze     = (const int*)d_in[0];
    const float* emb      = (const float*)d_in[1];
    const float* encode_w = (const float*)d_in[2];
    const float* encode_b = (const float*)d_in[3];
    const float* r_w      = (const float*)d_in[4];
    const float* q_w      = (const float*)d_in[5];
    const float* w_in     = (const float*)d_in[6];
    const float* fc_w     = (const float*)d_in[7];
    float* out = (float*)d_out;

    const int smem_bytes = (3 * VBUF + 8 * 2048 + 320 + 320 + 160 + 32 + 104 + 2 + 2)
                           * (int)sizeof(float);
    cudaFuncSetAttribute(vin_kernel,
                         cudaFuncAttributeMaxDynamicSharedMemorySize, smem_bytes);
    vin_kernel<<<NB * 2, NTH, smem_bytes>>>(maze, emb, encode_w, encode_b,
                                            r_w, q_w, w_in, fc_w, out);
}